// round 1
// baseline (speedup 1.0000x reference)
#include <cuda_runtime.h>
#include <math.h>

// ---------------------------------------------------------------------------
// Problem constants
// ---------------------------------------------------------------------------
#define BDIM 4
#define LDIM 2048
#define DDIM 512
#define HDIM 1024          // H = 2*D
#define MDIM (BDIM*LDIM)   // 8192 rows
#define RDIM 32
#define SDIM 16
#define ZCW  64            // R + 2S

// ---------------------------------------------------------------------------
// Scratch (static device globals: no allocations allowed)
// ---------------------------------------------------------------------------
__device__ float g_cln [MDIM*DDIM];     // LayerNorm(ctx)                16 MB
__device__ float g_z   [MDIM*2*HDIM];   // x @ Wa^T + ba  (u0|v0)        64 MB
__device__ float g_upre[MDIM*HDIM];     // u0 * (1+sigmoid(gate))        32 MB
__device__ float g_v   [MDIM*HDIM];     // v0 + q                        32 MB
__device__ float g_u   [MDIM*HDIM];     // silu(conv(upre))              32 MB
__device__ float g_zc  [MDIM*ZCW];      // u @ Wc^T                       2 MB
__device__ float g_dt  [MDIM*HDIM];     // softplus(...)                 32 MB
__device__ float g_y   [MDIM*HDIM];     // scan out * silu(v)            32 MB

// ---------------------------------------------------------------------------
// LayerNorm over D=512, one row per block (128 threads, float4 each)
// ---------------------------------------------------------------------------
__global__ __launch_bounds__(128) void ln_kernel(
    const float* __restrict__ ctx, const float* __restrict__ w,
    const float* __restrict__ beta, float* __restrict__ out)
{
    const int row = blockIdx.x;
    const int t   = threadIdx.x;
    const float4 v = reinterpret_cast<const float4*>(ctx + (size_t)row * DDIM)[t];
    float s  = v.x + v.y + v.z + v.w;
    float sq = v.x*v.x + v.y*v.y + v.z*v.z + v.w*v.w;
    #pragma unroll
    for (int o = 16; o > 0; o >>= 1) {
        s  += __shfl_xor_sync(0xffffffffu, s,  o);
        sq += __shfl_xor_sync(0xffffffffu, sq, o);
    }
    __shared__ float rs[4], rq[4];
    const int wid = t >> 5, lane = t & 31;
    if (lane == 0) { rs[wid] = s; rq[wid] = sq; }
    __syncthreads();
    s  = rs[0] + rs[1] + rs[2] + rs[3];
    sq = rq[0] + rq[1] + rq[2] + rq[3];
    const float mu  = s * (1.0f / DDIM);
    const float var = fmaxf(sq * (1.0f / DDIM) - mu * mu, 0.0f);
    const float inv = rsqrtf(var + 1e-5f);
    const float4 ww = reinterpret_cast<const float4*>(w)[t];
    const float4 bb = reinterpret_cast<const float4*>(beta)[t];
    float4 o;
    o.x = (v.x - mu) * inv * ww.x + bb.x;
    o.y = (v.y - mu) * inv * ww.y + bb.y;
    o.z = (v.z - mu) * inv * ww.z + bb.z;
    o.w = (v.w - mu) * inv * ww.w + bb.w;
    reinterpret_cast<float4*>(out + (size_t)row * DDIM)[t] = o;
}

// ---------------------------------------------------------------------------
// Generic fp32 SIMT GEMM:  C[M,N] = A[M,K] * W[N,K]^T   (+ epilogue)
// 128x128 tile, BK=8, 256 threads, 8x8 per thread, double-buffered smem.
// EPI: 0=+bias  1=u-gate  2=v-gate  3=plain  4=softplus(+bias)
// ---------------------------------------------------------------------------
#define GBM 128
#define GBN 128
#define GBK 8

template<int EPI>
__global__ __launch_bounds__(256) void gemm_k(
    const float* __restrict__ A, int lda,
    const float* __restrict__ W, int ldw,
    float* __restrict__ C, int ldc,
    int M, int N, int K,
    const float* __restrict__ bias,
    const float* __restrict__ aux, int ldaux)
{
    __shared__ float As[2][GBK][GBM + 4];
    __shared__ float Bs[2][GBK][GBN + 4];

    const int tid  = threadIdx.x;
    const int bm   = blockIdx.y * GBM;
    const int bn   = blockIdx.x * GBN;
    const int lrow = tid >> 1;           // 0..127
    const int lcol = (tid & 1) * 4;      // 0 or 4

    const float* Ag = A + (size_t)(bm + lrow) * lda + lcol;
    const int    wr = bn + lrow;
    const float* Wg = W + (size_t)wr * ldw + lcol;
    const bool   wok = (wr < N);

    float4 av = *reinterpret_cast<const float4*>(Ag);
    float4 wv = wok ? *reinterpret_cast<const float4*>(Wg)
                    : make_float4(0.f, 0.f, 0.f, 0.f);

    // stage tile 0
    As[0][lcol+0][lrow] = av.x; As[0][lcol+1][lrow] = av.y;
    As[0][lcol+2][lrow] = av.z; As[0][lcol+3][lrow] = av.w;
    Bs[0][lcol+0][lrow] = wv.x; Bs[0][lcol+1][lrow] = wv.y;
    Bs[0][lcol+2][lrow] = wv.z; Bs[0][lcol+3][lrow] = wv.w;
    __syncthreads();

    float acc[8][8];
    #pragma unroll
    for (int i = 0; i < 8; i++)
        #pragma unroll
        for (int j = 0; j < 8; j++) acc[i][j] = 0.f;

    const int r = ((tid >> 4) & 15) * 8;  // 0..120
    const int c = (tid & 15) * 8;         // 0..120
    int buf = 0;

    for (int k0 = 0; k0 < K; k0 += GBK) {
        const bool hn = (k0 + GBK) < K;
        if (hn) {
            av = *reinterpret_cast<const float4*>(Ag + k0 + GBK);
            wv = wok ? *reinterpret_cast<const float4*>(Wg + k0 + GBK)
                     : make_float4(0.f, 0.f, 0.f, 0.f);
        }
        #pragma unroll
        for (int kk = 0; kk < GBK; kk++) {
            float a[8], b[8];
            *reinterpret_cast<float4*>(a)     = *reinterpret_cast<const float4*>(&As[buf][kk][r]);
            *reinterpret_cast<float4*>(a + 4) = *reinterpret_cast<const float4*>(&As[buf][kk][r + 4]);
            *reinterpret_cast<float4*>(b)     = *reinterpret_cast<const float4*>(&Bs[buf][kk][c]);
            *reinterpret_cast<float4*>(b + 4) = *reinterpret_cast<const float4*>(&Bs[buf][kk][c + 4]);
            #pragma unroll
            for (int i = 0; i < 8; i++)
                #pragma unroll
                for (int j = 0; j < 8; j++)
                    acc[i][j] += a[i] * b[j];
        }
        if (hn) {
            const int nb = buf ^ 1;
            As[nb][lcol+0][lrow] = av.x; As[nb][lcol+1][lrow] = av.y;
            As[nb][lcol+2][lrow] = av.z; As[nb][lcol+3][lrow] = av.w;
            Bs[nb][lcol+0][lrow] = wv.x; Bs[nb][lcol+1][lrow] = wv.y;
            Bs[nb][lcol+2][lrow] = wv.z; Bs[nb][lcol+3][lrow] = wv.w;
            __syncthreads();
            buf = nb;
        }
    }

    #pragma unroll
    for (int i = 0; i < 8; i++) {
        const int m = bm + r + i;
        float* Cr = C + (size_t)m * ldc;
        #pragma unroll
        for (int j = 0; j < 8; j++) {
            const int n = bn + c + j;
            if (n < N) {
                float val = acc[i][j];
                if (EPI == 0) {
                    val += bias[n];
                } else if (EPI == 1) {        // u-gate: z_u * (1 + sigmoid(p))
                    const float p  = val + bias[n];
                    const float sg = 1.0f / (1.0f + __expf(-p));
                    val = aux[(size_t)m * ldaux + n] * (1.0f + sg);
                } else if (EPI == 2) {        // v-gate: z_v + q
                    val = aux[(size_t)m * ldaux + n + HDIM] + val + bias[n];
                } else if (EPI == 4) {        // softplus
                    const float xx = val + bias[n];
                    val = (xx > 20.0f) ? xx : log1pf(__expf(xx));
                }
                Cr[n] = val;
            }
        }
    }
}

// ---------------------------------------------------------------------------
// Causal depthwise conv (k=3) + SiLU:  one thread per (b,l,h) element.
// ---------------------------------------------------------------------------
__global__ __launch_bounds__(256) void conv_silu_kernel(
    const float* __restrict__ up, const float* __restrict__ cw,
    const float* __restrict__ cb, float* __restrict__ out)
{
    const int idx = blockIdx.x * blockDim.x + threadIdx.x;  // B*L*H
    const int h  = idx & (HDIM - 1);
    const int bl = idx >> 10;
    const int l  = bl & (LDIM - 1);
    const float w0 = cw[h * 3 + 0];
    const float w1 = cw[h * 3 + 1];
    const float w2 = cw[h * 3 + 2];
    const float x2 = up[idx];
    const float x1 = (l >= 1) ? up[idx - HDIM]     : 0.f;
    const float x0 = (l >= 2) ? up[idx - 2 * HDIM] : 0.f;
    const float s = w0 * x0 + w1 * x1 + w2 * x2 + cb[h];
    out[idx] = s * (1.0f / (1.0f + __expf(-s)));   // silu
}

// ---------------------------------------------------------------------------
// Selective scan: half-warp (16 lanes = 16 states) per (b,h) sequence.
// y[b,t,h] = (sum_s x_s * c_s + u*g) * silu(v)
// ---------------------------------------------------------------------------
__global__ __launch_bounds__(256) void scan_kernel(
    const float* __restrict__ u,   const float* __restrict__ dt,
    const float* __restrict__ zc,  const float* __restrict__ flog,
    const float* __restrict__ g,   const float* __restrict__ v,
    float* __restrict__ y)
{
    const int tid = blockIdx.x * blockDim.x + threadIdx.x;
    const int seq = tid >> 4;                  // 0 .. B*H-1
    const int s   = tid & 15;
    const int b   = seq >> 10;                 // /HDIM
    const int h   = seq & (HDIM - 1);

    const float a  = -__expf(flog[h * SDIM + s]);
    const float gh = g[h];

    const float* dtp = dt + (size_t)b * LDIM * HDIM + h;
    const float* up  = u  + (size_t)b * LDIM * HDIM + h;
    const float* vp  = v  + (size_t)b * LDIM * HDIM + h;
    float*       yp  = y  + (size_t)b * LDIM * HDIM + h;
    const float* zcp = zc + (size_t)b * LDIM * ZCW;

    float x = 0.f;
    // software-pipelined loads
    float d_c  = dtp[0];
    float u_c  = up[0];
    float b_c  = zcp[RDIM + s];
    float c_c  = zcp[RDIM + SDIM + s];

    #pragma unroll 2
    for (int t = 0; t < LDIM; t++) {
        float d_n = 0.f, u_n = 0.f, b_n = 0.f, c_n = 0.f;
        if (t + 1 < LDIM) {
            const int tn = t + 1;
            d_n = dtp[tn * HDIM];
            u_n = up [tn * HDIM];
            b_n = zcp[tn * ZCW + RDIM + s];
            c_n = zcp[tn * ZCW + RDIM + SDIM + s];
        }
        const float aa = __expf(d_c * a);
        x = aa * x + (d_c * u_c) * b_c;
        float ys = x * c_c;
        ys += __shfl_xor_sync(0xffffffffu, ys, 8);
        ys += __shfl_xor_sync(0xffffffffu, ys, 4);
        ys += __shfl_xor_sync(0xffffffffu, ys, 2);
        ys += __shfl_xor_sync(0xffffffffu, ys, 1);
        if (s == 0) {
            const float vv = vp[t * HDIM];
            const float sv = vv * (1.0f / (1.0f + __expf(-vv)));
            yp[t * HDIM] = (ys + u_c * gh) * sv;
        }
        d_c = d_n; u_c = u_n; b_c = b_n; c_c = c_n;
    }
}

// ---------------------------------------------------------------------------
// Launch
// ---------------------------------------------------------------------------
extern "C" void kernel_launch(void* const* d_in, const int* in_sizes, int n_in,
                              void* d_out, int out_size)
{
    const float* x      = (const float*)d_in[0];
    const float* ctx    = (const float*)d_in[1];
    const float* Wa     = (const float*)d_in[2];
    const float* ba     = (const float*)d_in[3];
    const float* conv_w = (const float*)d_in[4];
    const float* conv_b = (const float*)d_in[5];
    const float* Wc     = (const float*)d_in[6];
    const float* We     = (const float*)d_in[7];
    const float* be     = (const float*)d_in[8];
    const float* f_log  = (const float*)d_in[9];
    const float* g      = (const float*)d_in[10];
    const float* Wi     = (const float*)d_in[11];
    const float* bi     = (const float*)d_in[12];
    const float* ln_w   = (const float*)d_in[13];
    const float* ln_b   = (const float*)d_in[14];
    const float* Wgb    = (const float*)d_in[15];
    const float* bgb    = (const float*)d_in[16];
    const float* Wgc    = (const float*)d_in[17];
    const float* bgc    = (const float*)d_in[18];
    float* out = (float*)d_out;

    float *cln, *z, *upre, *v, *u, *zc, *dt, *y;
    cudaGetSymbolAddress((void**)&cln,  g_cln);
    cudaGetSymbolAddress((void**)&z,    g_z);
    cudaGetSymbolAddress((void**)&upre, g_upre);
    cudaGetSymbolAddress((void**)&v,    g_v);
    cudaGetSymbolAddress((void**)&u,    g_u);
    cudaGetSymbolAddress((void**)&zc,   g_zc);
    cudaGetSymbolAddress((void**)&dt,   g_dt);
    cudaGetSymbolAddress((void**)&y,    g_y);

    // 1. LayerNorm(ctx)
    ln_kernel<<<MDIM, 128>>>(ctx, ln_w, ln_b, cln);

    // 2. z = x @ Wa^T + ba               [8192 x 2048], K=512
    gemm_k<0><<<dim3(2*HDIM/GBN, MDIM/GBM), 256>>>(
        x, DDIM, Wa, DDIM, z, 2*HDIM, MDIM, 2*HDIM, DDIM, ba, nullptr, 0);

    // 3. u_pre = z_u * (1+sigmoid(cln@Wgb^T+bgb))   [8192 x 1024], K=512
    gemm_k<1><<<dim3(HDIM/GBN, MDIM/GBM), 256>>>(
        cln, DDIM, Wgb, DDIM, upre, HDIM, MDIM, HDIM, DDIM, bgb, z, 2*HDIM);

    // 4. v = z_v + cln@Wgc^T + bgc       [8192 x 1024], K=512
    gemm_k<2><<<dim3(HDIM/GBN, MDIM/GBM), 256>>>(
        cln, DDIM, Wgc, DDIM, v, HDIM, MDIM, HDIM, DDIM, bgc, z, 2*HDIM);

    // 5. u = silu(causal_conv3(u_pre))
    conv_silu_kernel<<<(MDIM*HDIM)/256, 256>>>(upre, conv_w, conv_b, u);

    // 6. zc = u @ Wc^T                   [8192 x 64], K=1024
    gemm_k<3><<<dim3(1, MDIM/GBM), 256>>>(
        u, HDIM, Wc, HDIM, zc, ZCW, MDIM, ZCW, HDIM, nullptr, nullptr, 0);

    // 7. dt = softplus(zc[:, :32] @ We^T + be)   [8192 x 1024], K=32
    gemm_k<4><<<dim3(HDIM/GBN, MDIM/GBM), 256>>>(
        zc, ZCW, We, RDIM, dt, HDIM, MDIM, HDIM, RDIM, be, nullptr, 0);

    // 8. selective scan + silu(v) gate -> y
    scan_kernel<<<(BDIM*HDIM*SDIM)/256, 256>>>(u, dt, zc, f_log, g, v, y);

    // 9. out = y @ Wi^T + bi             [8192 x 512], K=1024
    gemm_k<0><<<dim3(DDIM/GBN, MDIM/GBM), 256>>>(
        y, HDIM, Wi, HDIM, out, DDIM, MDIM, DDIM, HDIM, bi, nullptr, 0);
}

// round 3
// speedup vs baseline: 1.1793x; 1.1793x over previous
#include <cuda_runtime.h>
#include <cuda_bf16.h>
#include <math.h>
#include <stdint.h>

// ---------------------------------------------------------------------------
// Problem constants
// ---------------------------------------------------------------------------
#define BDIM 4
#define LDIM 2048
#define DDIM 512
#define HDIM 1024          // H = 2*D
#define MDIM (BDIM*LDIM)   // 8192 rows
#define RDIM 32
#define SDIM 16
#define ZCW  64            // R + 2S

// ---------------------------------------------------------------------------
// Scratch (static device globals: no allocations allowed)
// ---------------------------------------------------------------------------
__device__ float g_cln [MDIM*DDIM];
__device__ float g_z   [MDIM*2*HDIM];
__device__ float g_upre[MDIM*HDIM];
__device__ float g_v   [MDIM*HDIM];
__device__ float g_u   [MDIM*HDIM];
__device__ float g_zc  [MDIM*ZCW];
__device__ float g_dt  [MDIM*HDIM];
__device__ float g_y   [MDIM*HDIM];

// ---------------------------------------------------------------------------
// mma.sync / ldmatrix helpers (sm_80+ baseline ISA, legal on compute_100)
// ---------------------------------------------------------------------------
__device__ __forceinline__ uint32_t smem_u32(const void* p) {
    uint32_t a;
    asm("{ .reg .u64 t; cvta.to.shared.u64 t, %1; cvt.u32.u64 %0, t; }"
        : "=r"(a) : "l"(p));
    return a;
}

#define LDSM_X4(r0, r1, r2, r3, addr) \
    asm volatile("ldmatrix.sync.aligned.m8n8.x4.shared.b16 {%0,%1,%2,%3}, [%4];" \
        : "=r"(r0), "=r"(r1), "=r"(r2), "=r"(r3) : "r"(addr))

#define LDSM_X2(r0, r1, addr) \
    asm volatile("ldmatrix.sync.aligned.m8n8.x2.shared.b16 {%0,%1}, [%2];" \
        : "=r"(r0), "=r"(r1) : "r"(addr))

#define MMA16816(c, a, b) \
    asm volatile("mma.sync.aligned.m16n8k16.row.col.f32.bf16.bf16.f32 " \
        "{%0,%1,%2,%3}, {%4,%5,%6,%7}, {%8,%9}, {%0,%1,%2,%3};" \
        : "+f"((c)[0]), "+f"((c)[1]), "+f"((c)[2]), "+f"((c)[3]) \
        : "r"((a)[0]), "r"((a)[1]), "r"((a)[2]), "r"((a)[3]), \
          "r"((b)[0]), "r"((b)[1]))

#define SW128(o) ((o) ^ (((o) >> 3) & 0x70))

// ---------------------------------------------------------------------------
// Tensor-core GEMM:  C[M, N] = A[M, K] * W[N, K]^T  (+ epilogue), fp32 I/O.
// bf16 hi/lo split (3 MMA passes): error ~2^-18, rel_err ~1e-5.
// CTA tile 128 x N_TILE, K-chunk 64, 256 threads (8 warps).
// EPI: 0=+bias  1=u-gate  2=v-gate  3=plain  4=softplus(+bias)
// ---------------------------------------------------------------------------
template<int N_TILE, int EPI>
__global__ __launch_bounds__(256) void mma_gemm(
    const float* __restrict__ A, int lda,
    const float* __restrict__ W, int ldw,
    float* __restrict__ C, int ldc,
    int K,
    const float* __restrict__ bias,
    const float* __restrict__ aux, int ldaux)
{
    constexpr int WM  = (N_TILE == 128) ? 64 : 32;   // warp M tile
    constexpr int WN  = 32;                          // warp N tile
    constexpr int WGM = 128 / WM;                    // warps along M
    constexpr int MT  = WM / 16;                     // m16 tiles per warp
    constexpr int NT  = WN / 8;                      // n8 tiles per warp

    extern __shared__ char dsm[];
    char* sb = (char*)((((uintptr_t)dsm) + 1023) & ~(uintptr_t)1023);
    const uint32_t sb32 = smem_u32(sb);

    constexpr int ASZ = 128 * 128;        // 128 rows x 64 bf16 = 16 KB
    constexpr int BSZ = N_TILE * 128;
    char* pAH = sb;
    char* pAL = sb + ASZ;
    char* pBH = sb + 2 * ASZ;
    char* pBL = sb + 2 * ASZ + BSZ;
    const uint32_t aAH = sb32;
    const uint32_t aAL = sb32 + ASZ;
    const uint32_t aBH = sb32 + 2 * ASZ;
    const uint32_t aBL = sb32 + 2 * ASZ + BSZ;

    const int tid  = threadIdx.x;
    const int lane = tid & 31;
    const int w    = tid >> 5;
    const int bm   = blockIdx.y * 128;
    const int bn   = blockIdx.x * N_TILE;
    const int wm   = (w % WGM) * WM;
    const int wn   = (w / WGM) * WN;

    float acc[MT][NT][4];
    #pragma unroll
    for (int mi = 0; mi < MT; mi++)
        #pragma unroll
        for (int ni = 0; ni < NT; ni++)
            #pragma unroll
            for (int q = 0; q < 4; q++) acc[mi][ni][q] = 0.f;

    // ldmatrix lane -> byte offset bases (within tile, before k-step add)
    const int a_row  = wm + (lane & 15);
    const int a_half = (lane >> 4) * 16;          // bytes
    const int b_row  = wn + (lane & 7);
    const int b_half = ((lane >> 3) & 1) * 16;    // bytes

    union Cvt { __nv_bfloat162 b2[2]; uint2 u; };

    const int nst = (K + 63) >> 6;
    for (int st = 0; st < nst; st++) {
        const int k0 = st << 6;

        // ---- load + convert A tile (128 x 64 fp32 -> hi/lo bf16, SW128) ----
        #pragma unroll
        for (int i = 0; i < (128 * 16) / 256; i++) {
            const int idx = tid + i * 256;
            const int row = idx >> 4;
            const int kq  = idx & 15;
            const int kk  = k0 + kq * 4;
            float4 v = make_float4(0.f, 0.f, 0.f, 0.f);
            if (kk < K) v = *(const float4*)(A + (size_t)(bm + row) * lda + kk);
            const __nv_bfloat16 h0 = __float2bfloat16(v.x);
            const __nv_bfloat16 h1 = __float2bfloat16(v.y);
            const __nv_bfloat16 h2 = __float2bfloat16(v.z);
            const __nv_bfloat16 h3 = __float2bfloat16(v.w);
            Cvt hi, lo;
            hi.b2[0] = __halves2bfloat162(h0, h1);
            hi.b2[1] = __halves2bfloat162(h2, h3);
            lo.b2[0] = __halves2bfloat162(__float2bfloat16(v.x - __bfloat162float(h0)),
                                          __float2bfloat16(v.y - __bfloat162float(h1)));
            lo.b2[1] = __halves2bfloat162(__float2bfloat16(v.z - __bfloat162float(h2)),
                                          __float2bfloat16(v.w - __bfloat162float(h3)));
            const uint32_t off = SW128((uint32_t)(row * 128 + kq * 8));
            *(uint2*)(pAH + off) = hi.u;
            *(uint2*)(pAL + off) = lo.u;
        }
        // ---- load + convert W tile (N_TILE x 64) ----
        #pragma unroll
        for (int i = 0; i < (N_TILE * 16) / 256; i++) {
            const int idx = tid + i * 256;
            const int row = idx >> 4;
            const int kq  = idx & 15;
            const int kk  = k0 + kq * 4;
            float4 v = make_float4(0.f, 0.f, 0.f, 0.f);
            if (kk < K) v = *(const float4*)(W + (size_t)(bn + row) * ldw + kk);
            const __nv_bfloat16 h0 = __float2bfloat16(v.x);
            const __nv_bfloat16 h1 = __float2bfloat16(v.y);
            const __nv_bfloat16 h2 = __float2bfloat16(v.z);
            const __nv_bfloat16 h3 = __float2bfloat16(v.w);
            Cvt hi, lo;
            hi.b2[0] = __halves2bfloat162(h0, h1);
            hi.b2[1] = __halves2bfloat162(h2, h3);
            lo.b2[0] = __halves2bfloat162(__float2bfloat16(v.x - __bfloat162float(h0)),
                                          __float2bfloat16(v.y - __bfloat162float(h1)));
            lo.b2[1] = __halves2bfloat162(__float2bfloat16(v.z - __bfloat162float(h2)),
                                          __float2bfloat16(v.w - __bfloat162float(h3)));
            const uint32_t off = SW128((uint32_t)(row * 128 + kq * 8));
            *(uint2*)(pBH + off) = hi.u;
            *(uint2*)(pBL + off) = lo.u;
        }
        __syncthreads();

        // ---- MMA over 4 k16 steps, 3 hi/lo passes ----
        #pragma unroll
        for (int s = 0; s < 4; s++) {
            const uint32_t aoff = (uint32_t)(s * 32) + (uint32_t)a_half;
            const uint32_t boff = (uint32_t)(s * 32) + (uint32_t)b_half;

            uint32_t ah[MT][4], al[MT][4], bh[NT][2], bl[NT][2];
            #pragma unroll
            for (int mi = 0; mi < MT; mi++) {
                const uint32_t sw = SW128((uint32_t)((a_row + mi * 16) * 128) + aoff);
                LDSM_X4(ah[mi][0], ah[mi][1], ah[mi][2], ah[mi][3], aAH + sw);
                LDSM_X4(al[mi][0], al[mi][1], al[mi][2], al[mi][3], aAL + sw);
            }
            #pragma unroll
            for (int ni = 0; ni < NT; ni++) {
                const uint32_t sw = SW128((uint32_t)((b_row + ni * 8) * 128) + boff);
                LDSM_X2(bh[ni][0], bh[ni][1], aBH + sw);
                LDSM_X2(bl[ni][0], bl[ni][1], aBL + sw);
            }
            #pragma unroll
            for (int mi = 0; mi < MT; mi++)
                #pragma unroll
                for (int ni = 0; ni < NT; ni++) {
                    MMA16816(acc[mi][ni], ah[mi], bh[ni]);
                    MMA16816(acc[mi][ni], ah[mi], bl[ni]);
                    MMA16816(acc[mi][ni], al[mi], bh[ni]);
                }
        }
        __syncthreads();
    }

    // ---- epilogue: registers -> C with EPI ----
    const int q  = lane >> 2;            // 0..7
    const int nn = (lane & 3) * 2;       // 0,2,4,6
    #pragma unroll
    for (int mi = 0; mi < MT; mi++) {
        #pragma unroll
        for (int half = 0; half < 2; half++) {
            const int m = bm + wm + mi * 16 + q + half * 8;
            float* Cr = C + (size_t)m * ldc;
            const float* auxr = (EPI == 1 || EPI == 2)
                ? (aux + (size_t)m * ldaux + (EPI == 2 ? HDIM : 0)) : nullptr;
            #pragma unroll
            for (int ni = 0; ni < NT; ni++) {
                const int n = bn + wn + ni * 8 + nn;
                float r0 = acc[mi][ni][half * 2 + 0];
                float r1 = acc[mi][ni][half * 2 + 1];
                if (EPI != 3) {
                    const float b0 = bias[n], b1 = bias[n + 1];
                    if (EPI == 0) {
                        r0 += b0; r1 += b1;
                    } else if (EPI == 1) {
                        const float p0 = r0 + b0, p1 = r1 + b1;
                        r0 = auxr[n] * (1.f + 1.f / (1.f + __expf(-p0)));
                        r1 = auxr[n + 1] * (1.f + 1.f / (1.f + __expf(-p1)));
                    } else if (EPI == 2) {
                        r0 = auxr[n] + r0 + b0;
                        r1 = auxr[n + 1] + r1 + b1;
                    } else {  // softplus
                        const float x0 = r0 + b0, x1 = r1 + b1;
                        r0 = (x0 > 20.f) ? x0 : log1pf(__expf(x0));
                        r1 = (x1 > 20.f) ? x1 : log1pf(__expf(x1));
                    }
                }
                *(float2*)(Cr + n) = make_float2(r0, r1);
            }
        }
    }
}

// ---------------------------------------------------------------------------
// LayerNorm over D=512
// ---------------------------------------------------------------------------
__global__ __launch_bounds__(128) void ln_kernel(
    const float* __restrict__ ctx, const float* __restrict__ w,
    const float* __restrict__ beta, float* __restrict__ out)
{
    const int row = blockIdx.x;
    const int t   = threadIdx.x;
    const float4 v = reinterpret_cast<const float4*>(ctx + (size_t)row * DDIM)[t];
    float s  = v.x + v.y + v.z + v.w;
    float sq = v.x*v.x + v.y*v.y + v.z*v.z + v.w*v.w;
    #pragma unroll
    for (int o = 16; o > 0; o >>= 1) {
        s  += __shfl_xor_sync(0xffffffffu, s,  o);
        sq += __shfl_xor_sync(0xffffffffu, sq, o);
    }
    __shared__ float rs[4], rq[4];
    const int wid = t >> 5, lane = t & 31;
    if (lane == 0) { rs[wid] = s; rq[wid] = sq; }
    __syncthreads();
    s  = rs[0] + rs[1] + rs[2] + rs[3];
    sq = rq[0] + rq[1] + rq[2] + rq[3];
    const float mu  = s * (1.0f / DDIM);
    const float var = fmaxf(sq * (1.0f / DDIM) - mu * mu, 0.0f);
    const float inv = rsqrtf(var + 1e-5f);
    const float4 ww = reinterpret_cast<const float4*>(w)[t];
    const float4 bb = reinterpret_cast<const float4*>(beta)[t];
    float4 o;
    o.x = (v.x - mu) * inv * ww.x + bb.x;
    o.y = (v.y - mu) * inv * ww.y + bb.y;
    o.z = (v.z - mu) * inv * ww.z + bb.z;
    o.w = (v.w - mu) * inv * ww.w + bb.w;
    reinterpret_cast<float4*>(out + (size_t)row * DDIM)[t] = o;
}

// ---------------------------------------------------------------------------
// Causal depthwise conv (k=3) + SiLU
// ---------------------------------------------------------------------------
__global__ __launch_bounds__(256) void conv_silu_kernel(
    const float* __restrict__ up, const float* __restrict__ cw,
    const float* __restrict__ cb, float* __restrict__ out)
{
    const int idx = blockIdx.x * blockDim.x + threadIdx.x;
    const int h  = idx & (HDIM - 1);
    const int bl = idx >> 10;
    const int l  = bl & (LDIM - 1);
    const float w0 = cw[h * 3 + 0];
    const float w1 = cw[h * 3 + 1];
    const float w2 = cw[h * 3 + 2];
    const float x2 = up[idx];
    const float x1 = (l >= 1) ? up[idx - HDIM]     : 0.f;
    const float x0 = (l >= 2) ? up[idx - 2 * HDIM] : 0.f;
    const float s = w0 * x0 + w1 * x1 + w2 * x2 + cb[h];
    out[idx] = s * (1.0f / (1.0f + __expf(-s)));
}

// ---------------------------------------------------------------------------
// Selective scan
// ---------------------------------------------------------------------------
__global__ __launch_bounds__(256) void scan_kernel(
    const float* __restrict__ u,   const float* __restrict__ dt,
    const float* __restrict__ zc,  const float* __restrict__ flog,
    const float* __restrict__ g,   const float* __restrict__ v,
    float* __restrict__ y)
{
    const int tid = blockIdx.x * blockDim.x + threadIdx.x;
    const int seq = tid >> 4;
    const int s   = tid & 15;
    const int b   = seq >> 10;
    const int h   = seq & (HDIM - 1);

    const float a  = -__expf(flog[h * SDIM + s]);
    const float gh = g[h];

    const float* dtp = dt + (size_t)b * LDIM * HDIM + h;
    const float* up  = u  + (size_t)b * LDIM * HDIM + h;
    const float* vp  = v  + (size_t)b * LDIM * HDIM + h;
    float*       yp  = y  + (size_t)b * LDIM * HDIM + h;
    const float* zcp = zc + (size_t)b * LDIM * ZCW;

    float x = 0.f;
    float d_c  = dtp[0];
    float u_c  = up[0];
    float b_c  = zcp[RDIM + s];
    float c_c  = zcp[RDIM + SDIM + s];

    #pragma unroll 2
    for (int t = 0; t < LDIM; t++) {
        float d_n = 0.f, u_n = 0.f, b_n = 0.f, c_n = 0.f;
        if (t + 1 < LDIM) {
            const int tn = t + 1;
            d_n = dtp[tn * HDIM];
            u_n = up [tn * HDIM];
            b_n = zcp[tn * ZCW + RDIM + s];
            c_n = zcp[tn * ZCW + RDIM + SDIM + s];
        }
        const float aa = __expf(d_c * a);
        x = aa * x + (d_c * u_c) * b_c;
        float ys = x * c_c;
        ys += __shfl_xor_sync(0xffffffffu, ys, 8);
        ys += __shfl_xor_sync(0xffffffffu, ys, 4);
        ys += __shfl_xor_sync(0xffffffffu, ys, 2);
        ys += __shfl_xor_sync(0xffffffffu, ys, 1);
        if (s == 0) {
            const float vv = vp[t * HDIM];
            const float sv = vv * (1.0f / (1.0f + __expf(-vv)));
            yp[t * HDIM] = (ys + u_c * gh) * sv;
        }
        d_c = d_n; u_c = u_n; b_c = b_n; c_c = c_n;
    }
}

// ---------------------------------------------------------------------------
// Launch
// ---------------------------------------------------------------------------
extern "C" void kernel_launch(void* const* d_in, const int* in_sizes, int n_in,
                              void* d_out, int out_size)
{
    const float* x      = (const float*)d_in[0];
    const float* ctx    = (const float*)d_in[1];
    const float* Wa     = (const float*)d_in[2];
    const float* ba     = (const float*)d_in[3];
    const float* conv_w = (const float*)d_in[4];
    const float* conv_b = (const float*)d_in[5];
    const float* Wc     = (const float*)d_in[6];
    const float* We     = (const float*)d_in[7];
    const float* be     = (const float*)d_in[8];
    const float* f_log  = (const float*)d_in[9];
    const float* g      = (const float*)d_in[10];
    const float* Wi     = (const float*)d_in[11];
    const float* bi     = (const float*)d_in[12];
    const float* ln_w   = (const float*)d_in[13];
    const float* ln_b   = (const float*)d_in[14];
    const float* Wgb    = (const float*)d_in[15];
    const float* bgb    = (const float*)d_in[16];
    const float* Wgc    = (const float*)d_in[17];
    const float* bgc    = (const float*)d_in[18];
    float* out = (float*)d_out;

    float *cln, *z, *upre, *v, *u, *zc, *dt, *y;
    cudaGetSymbolAddress((void**)&cln,  g_cln);
    cudaGetSymbolAddress((void**)&z,    g_z);
    cudaGetSymbolAddress((void**)&upre, g_upre);
    cudaGetSymbolAddress((void**)&v,    g_v);
    cudaGetSymbolAddress((void**)&u,    g_u);
    cudaGetSymbolAddress((void**)&zc,   g_zc);
    cudaGetSymbolAddress((void**)&dt,   g_dt);
    cudaGetSymbolAddress((void**)&y,    g_y);

    const int SM128 = 1024 + 2 * 16384 + 2 * 128 * 128;  // 66560
    const int SM64  = 1024 + 2 * 16384 + 2 *  64 * 128;  // 50176
    cudaFuncSetAttribute(mma_gemm<128, 0>, cudaFuncAttributeMaxDynamicSharedMemorySize, SM128);
    cudaFuncSetAttribute(mma_gemm<128, 1>, cudaFuncAttributeMaxDynamicSharedMemorySize, SM128);
    cudaFuncSetAttribute(mma_gemm<128, 2>, cudaFuncAttributeMaxDynamicSharedMemorySize, SM128);
    cudaFuncSetAttribute(mma_gemm<128, 4>, cudaFuncAttributeMaxDynamicSharedMemorySize, SM128);
    cudaFuncSetAttribute(mma_gemm<64, 3>,  cudaFuncAttributeMaxDynamicSharedMemorySize, SM64);

    // 1. LayerNorm(ctx)
    ln_kernel<<<MDIM, 128>>>(ctx, ln_w, ln_b, cln);

    // 2. z = x @ Wa^T + ba               [8192 x 2048], K=512
    mma_gemm<128, 0><<<dim3(2 * HDIM / 128, MDIM / 128), 256, SM128>>>(
        x, DDIM, Wa, DDIM, z, 2 * HDIM, DDIM, ba, nullptr, 0);

    // 3. u_pre = z_u * (1 + sigmoid(cln @ Wgb^T + bgb))
    mma_gemm<128, 1><<<dim3(HDIM / 128, MDIM / 128), 256, SM128>>>(
        cln, DDIM, Wgb, DDIM, upre, HDIM, DDIM, bgb, z, 2 * HDIM);

    // 4. v = z_v + cln @ Wgc^T + bgc
    mma_gemm<128, 2><<<dim3(HDIM / 128, MDIM / 128), 256, SM128>>>(
        cln, DDIM, Wgc, DDIM, v, HDIM, DDIM, bgc, z, 2 * HDIM);

    // 5. u = silu(causal_conv3(u_pre))
    conv_silu_kernel<<<(MDIM * HDIM) / 256, 256>>>(upre, conv_w, conv_b, u);

    // 6. zc = u @ Wc^T                   [8192 x 64], K=1024
    mma_gemm<64, 3><<<dim3(1, MDIM / 128), 256, SM64>>>(
        u, HDIM, Wc, HDIM, zc, ZCW, HDIM, nullptr, nullptr, 0);

    // 7. dt = softplus(zc[:, :32] @ We^T + be)   [8192 x 1024], K=32
    mma_gemm<128, 4><<<dim3(HDIM / 128, MDIM / 128), 256, SM128>>>(
        zc, ZCW, We, RDIM, dt, HDIM, RDIM, be, nullptr, 0);

    // 8. selective scan + silu(v) gate -> y
    scan_kernel<<<(BDIM * HDIM * SDIM) / 256, 256>>>(u, dt, zc, f_log, g, v, y);

    // 9. out = y @ Wi^T + bi             [8192 x 512], K=1024
    mma_gemm<128, 0><<<dim3(DDIM / 128, MDIM / 128), 256, SM128>>>(
        y, HDIM, Wi, HDIM, out, DDIM, HDIM, bi, nullptr, 0);
}

// round 4
// speedup vs baseline: 1.1851x; 1.0050x over previous
#include <cuda_runtime.h>
#include <cuda_bf16.h>
#include <math.h>
#include <stdint.h>

// ---------------------------------------------------------------------------
// Problem constants
// ---------------------------------------------------------------------------
#define BDIM 4
#define LDIM 2048
#define DDIM 512
#define HDIM 1024          // H = 2*D
#define MDIM (BDIM*LDIM)   // 8192 rows
#define RDIM 32
#define SDIM 16
#define ZCW  64            // R + 2S

// ---------------------------------------------------------------------------
// Scratch (static device globals: no allocations allowed)
// ---------------------------------------------------------------------------
__device__ float g_cln [MDIM*DDIM];
__device__ float g_z   [MDIM*2*HDIM];
__device__ float g_upre[MDIM*HDIM];
__device__ float g_v   [MDIM*HDIM];
__device__ float g_u   [MDIM*HDIM];
__device__ float g_zc  [MDIM*ZCW];
__device__ float g_dt  [MDIM*HDIM];
__device__ float g_y   [MDIM*HDIM];

// ---------------------------------------------------------------------------
// mma.sync / ldmatrix helpers (sm_80+ baseline ISA, legal on compute_100)
// ---------------------------------------------------------------------------
__device__ __forceinline__ uint32_t smem_u32(const void* p) {
    uint32_t a;
    asm("{ .reg .u64 t; cvta.to.shared.u64 t, %1; cvt.u32.u64 %0, t; }"
        : "=r"(a) : "l"(p));
    return a;
}

#define LDSM_X4(r0, r1, r2, r3, addr) \
    asm volatile("ldmatrix.sync.aligned.m8n8.x4.shared.b16 {%0,%1,%2,%3}, [%4];" \
        : "=r"(r0), "=r"(r1), "=r"(r2), "=r"(r3) : "r"(addr))

#define LDSM_X2(r0, r1, addr) \
    asm volatile("ldmatrix.sync.aligned.m8n8.x2.shared.b16 {%0,%1}, [%2];" \
        : "=r"(r0), "=r"(r1) : "r"(addr))

#define MMA16816(c, a, b) \
    asm volatile("mma.sync.aligned.m16n8k16.row.col.f32.bf16.bf16.f32 " \
        "{%0,%1,%2,%3}, {%4,%5,%6,%7}, {%8,%9}, {%0,%1,%2,%3};" \
        : "+f"((c)[0]), "+f"((c)[1]), "+f"((c)[2]), "+f"((c)[3]) \
        : "r"((a)[0]), "r"((a)[1]), "r"((a)[2]), "r"((a)[3]), \
          "r"((b)[0]), "r"((b)[1]))

#define SW128(o) ((o) ^ (((o) >> 3) & 0x70))

// ---------------------------------------------------------------------------
// Tensor-core GEMM:  C[M, N] = A[M, K] * W[N, K]^T  (+ epilogue), fp32 I/O.
// bf16 hi/lo split (3 MMA passes): error ~2^-18, rel_err ~1e-5.
// CTA tile 128 x N_TILE, K-chunk 64, 256 threads (8 warps).
// EPI: 0=+bias  1=u-gate  2=v-gate  3=plain  4=softplus(+bias)
// ---------------------------------------------------------------------------
template<int N_TILE, int EPI>
__global__ __launch_bounds__(256) void mma_gemm(
    const float* __restrict__ A, int lda,
    const float* __restrict__ W, int ldw,
    float* __restrict__ C, int ldc,
    int K,
    const float* __restrict__ bias,
    const float* __restrict__ aux, int ldaux)
{
    constexpr int WM  = (N_TILE == 128) ? 64 : 32;   // warp M tile
    constexpr int WN  = 32;                          // warp N tile
    constexpr int WGM = 128 / WM;                    // warps along M
    constexpr int MT  = WM / 16;                     // m16 tiles per warp
    constexpr int NT  = WN / 8;                      // n8 tiles per warp

    extern __shared__ char dsm[];
    char* sb = (char*)((((uintptr_t)dsm) + 1023) & ~(uintptr_t)1023);
    const uint32_t sb32 = smem_u32(sb);

    constexpr int ASZ = 128 * 128;        // 128 rows x 64 bf16 = 16 KB
    constexpr int BSZ = N_TILE * 128;
    char* pAH = sb;
    char* pAL = sb + ASZ;
    char* pBH = sb + 2 * ASZ;
    char* pBL = sb + 2 * ASZ + BSZ;
    const uint32_t aAH = sb32;
    const uint32_t aAL = sb32 + ASZ;
    const uint32_t aBH = sb32 + 2 * ASZ;
    const uint32_t aBL = sb32 + 2 * ASZ + BSZ;

    const int tid  = threadIdx.x;
    const int lane = tid & 31;
    const int w    = tid >> 5;
    const int bm   = blockIdx.y * 128;
    const int bn   = blockIdx.x * N_TILE;
    const int wm   = (w % WGM) * WM;
    const int wn   = (w / WGM) * WN;

    float acc[MT][NT][4];
    #pragma unroll
    for (int mi = 0; mi < MT; mi++)
        #pragma unroll
        for (int ni = 0; ni < NT; ni++)
            #pragma unroll
            for (int q = 0; q < 4; q++) acc[mi][ni][q] = 0.f;

    // ldmatrix lane -> byte offset bases (within tile, before k-step add)
    const int a_row  = wm + (lane & 15);
    const int a_half = (lane >> 4) * 16;          // bytes
    const int b_row  = wn + (lane & 7);
    const int b_half = ((lane >> 3) & 1) * 16;    // bytes

    union Cvt { __nv_bfloat162 b2[2]; uint2 u; };

    const int nst = (K + 63) >> 6;
    for (int st = 0; st < nst; st++) {
        const int k0 = st << 6;

        // ---- load + convert A tile (128 x 64 fp32 -> hi/lo bf16, SW128) ----
        #pragma unroll
        for (int i = 0; i < (128 * 16) / 256; i++) {
            const int idx = tid + i * 256;
            const int row = idx >> 4;
            const int kq  = idx & 15;
            const int kk  = k0 + kq * 4;
            float4 v = make_float4(0.f, 0.f, 0.f, 0.f);
            if (kk < K) v = *(const float4*)(A + (size_t)(bm + row) * lda + kk);
            const __nv_bfloat16 h0 = __float2bfloat16(v.x);
            const __nv_bfloat16 h1 = __float2bfloat16(v.y);
            const __nv_bfloat16 h2 = __float2bfloat16(v.z);
            const __nv_bfloat16 h3 = __float2bfloat16(v.w);
            Cvt hi, lo;
            hi.b2[0] = __halves2bfloat162(h0, h1);
            hi.b2[1] = __halves2bfloat162(h2, h3);
            lo.b2[0] = __halves2bfloat162(__float2bfloat16(v.x - __bfloat162float(h0)),
                                          __float2bfloat16(v.y - __bfloat162float(h1)));
            lo.b2[1] = __halves2bfloat162(__float2bfloat16(v.z - __bfloat162float(h2)),
                                          __float2bfloat16(v.w - __bfloat162float(h3)));
            const uint32_t off = SW128((uint32_t)(row * 128 + kq * 8));
            *(uint2*)(pAH + off) = hi.u;
            *(uint2*)(pAL + off) = lo.u;
        }
        // ---- load + convert W tile (N_TILE x 64) ----
        #pragma unroll
        for (int i = 0; i < (N_TILE * 16) / 256; i++) {
            const int idx = tid + i * 256;
            const int row = idx >> 4;
            const int kq  = idx & 15;
            const int kk  = k0 + kq * 4;
            float4 v = make_float4(0.f, 0.f, 0.f, 0.f);
            if (kk < K) v = *(const float4*)(W + (size_t)(bn + row) * ldw + kk);
            const __nv_bfloat16 h0 = __float2bfloat16(v.x);
            const __nv_bfloat16 h1 = __float2bfloat16(v.y);
            const __nv_bfloat16 h2 = __float2bfloat16(v.z);
            const __nv_bfloat16 h3 = __float2bfloat16(v.w);
            Cvt hi, lo;
            hi.b2[0] = __halves2bfloat162(h0, h1);
            hi.b2[1] = __halves2bfloat162(h2, h3);
            lo.b2[0] = __halves2bfloat162(__float2bfloat16(v.x - __bfloat162float(h0)),
                                          __float2bfloat16(v.y - __bfloat162float(h1)));
            lo.b2[1] = __halves2bfloat162(__float2bfloat16(v.z - __bfloat162float(h2)),
                                          __float2bfloat16(v.w - __bfloat162float(h3)));
            const uint32_t off = SW128((uint32_t)(row * 128 + kq * 8));
            *(uint2*)(pBH + off) = hi.u;
            *(uint2*)(pBL + off) = lo.u;
        }
        __syncthreads();

        // ---- MMA over 4 k16 steps, 3 hi/lo passes ----
        #pragma unroll
        for (int s = 0; s < 4; s++) {
            const uint32_t aoff = (uint32_t)(s * 32) + (uint32_t)a_half;
            const uint32_t boff = (uint32_t)(s * 32) + (uint32_t)b_half;

            uint32_t ah[MT][4], al[MT][4], bh[NT][2], bl[NT][2];
            #pragma unroll
            for (int mi = 0; mi < MT; mi++) {
                const uint32_t sw = SW128((uint32_t)((a_row + mi * 16) * 128) + aoff);
                LDSM_X4(ah[mi][0], ah[mi][1], ah[mi][2], ah[mi][3], aAH + sw);
                LDSM_X4(al[mi][0], al[mi][1], al[mi][2], al[mi][3], aAL + sw);
            }
            #pragma unroll
            for (int ni = 0; ni < NT; ni++) {
                const uint32_t sw = SW128((uint32_t)((b_row + ni * 8) * 128) + boff);
                LDSM_X2(bh[ni][0], bh[ni][1], aBH + sw);
                LDSM_X2(bl[ni][0], bl[ni][1], aBL + sw);
            }
            #pragma unroll
            for (int mi = 0; mi < MT; mi++)
                #pragma unroll
                for (int ni = 0; ni < NT; ni++) {
                    MMA16816(acc[mi][ni], ah[mi], bh[ni]);
                    MMA16816(acc[mi][ni], ah[mi], bl[ni]);
                    MMA16816(acc[mi][ni], al[mi], bh[ni]);
                }
        }
        __syncthreads();
    }

    // ---- epilogue: registers -> C with EPI ----
    const int q  = lane >> 2;            // 0..7
    const int nn = (lane & 3) * 2;       // 0,2,4,6
    #pragma unroll
    for (int mi = 0; mi < MT; mi++) {
        #pragma unroll
        for (int half = 0; half < 2; half++) {
            const int m = bm + wm + mi * 16 + q + half * 8;
            float* Cr = C + (size_t)m * ldc;
            const float* auxr = (EPI == 1 || EPI == 2)
                ? (aux + (size_t)m * ldaux + (EPI == 2 ? HDIM : 0)) : nullptr;
            #pragma unroll
            for (int ni = 0; ni < NT; ni++) {
                const int n = bn + wn + ni * 8 + nn;
                float r0 = acc[mi][ni][half * 2 + 0];
                float r1 = acc[mi][ni][half * 2 + 1];
                if (EPI != 3) {
                    const float b0 = bias[n], b1 = bias[n + 1];
                    if (EPI == 0) {
                        r0 += b0; r1 += b1;
                    } else if (EPI == 1) {
                        const float p0 = r0 + b0, p1 = r1 + b1;
                        r0 = auxr[n] * (1.f + 1.f / (1.f + __expf(-p0)));
                        r1 = auxr[n + 1] * (1.f + 1.f / (1.f + __expf(-p1)));
                    } else if (EPI == 2) {
                        r0 = auxr[n] + r0 + b0;
                        r1 = auxr[n + 1] + r1 + b1;
                    } else {  // softplus
                        const float x0 = r0 + b0, x1 = r1 + b1;
                        r0 = (x0 > 20.f) ? x0 : log1pf(__expf(x0));
                        r1 = (x1 > 20.f) ? x1 : log1pf(__expf(x1));
                    }
                }
                *(float2*)(Cr + n) = make_float2(r0, r1);
            }
        }
    }
}

// ---------------------------------------------------------------------------
// LayerNorm over D=512
// ---------------------------------------------------------------------------
__global__ __launch_bounds__(128) void ln_kernel(
    const float* __restrict__ ctx, const float* __restrict__ w,
    const float* __restrict__ beta, float* __restrict__ out)
{
    const int row = blockIdx.x;
    const int t   = threadIdx.x;
    const float4 v = reinterpret_cast<const float4*>(ctx + (size_t)row * DDIM)[t];
    float s  = v.x + v.y + v.z + v.w;
    float sq = v.x*v.x + v.y*v.y + v.z*v.z + v.w*v.w;
    #pragma unroll
    for (int o = 16; o > 0; o >>= 1) {
        s  += __shfl_xor_sync(0xffffffffu, s,  o);
        sq += __shfl_xor_sync(0xffffffffu, sq, o);
    }
    __shared__ float rs[4], rq[4];
    const int wid = t >> 5, lane = t & 31;
    if (lane == 0) { rs[wid] = s; rq[wid] = sq; }
    __syncthreads();
    s  = rs[0] + rs[1] + rs[2] + rs[3];
    sq = rq[0] + rq[1] + rq[2] + rq[3];
    const float mu  = s * (1.0f / DDIM);
    const float var = fmaxf(sq * (1.0f / DDIM) - mu * mu, 0.0f);
    const float inv = rsqrtf(var + 1e-5f);
    const float4 ww = reinterpret_cast<const float4*>(w)[t];
    const float4 bb = reinterpret_cast<const float4*>(beta)[t];
    float4 o;
    o.x = (v.x - mu) * inv * ww.x + bb.x;
    o.y = (v.y - mu) * inv * ww.y + bb.y;
    o.z = (v.z - mu) * inv * ww.z + bb.z;
    o.w = (v.w - mu) * inv * ww.w + bb.w;
    reinterpret_cast<float4*>(out + (size_t)row * DDIM)[t] = o;
}

// ---------------------------------------------------------------------------
// Causal depthwise conv (k=3) + SiLU
// ---------------------------------------------------------------------------
__global__ __launch_bounds__(256) void conv_silu_kernel(
    const float* __restrict__ up, const float* __restrict__ cw,
    const float* __restrict__ cb, float* __restrict__ out)
{
    const int idx = blockIdx.x * blockDim.x + threadIdx.x;
    const int h  = idx & (HDIM - 1);
    const int bl = idx >> 10;
    const int l  = bl & (LDIM - 1);
    const float w0 = cw[h * 3 + 0];
    const float w1 = cw[h * 3 + 1];
    const float w2 = cw[h * 3 + 2];
    const float x2 = up[idx];
    const float x1 = (l >= 1) ? up[idx - HDIM]     : 0.f;
    const float x0 = (l >= 2) ? up[idx - 2 * HDIM] : 0.f;
    const float s = w0 * x0 + w1 * x1 + w2 * x2 + cb[h];
    out[idx] = s * (1.0f / (1.0f + __expf(-s)));
}

// ---------------------------------------------------------------------------
// Selective scan
// ---------------------------------------------------------------------------
__global__ __launch_bounds__(256) void scan_kernel(
    const float* __restrict__ u,   const float* __restrict__ dt,
    const float* __restrict__ zc,  const float* __restrict__ flog,
    const float* __restrict__ g,   const float* __restrict__ v,
    float* __restrict__ y)
{
    const int tid = blockIdx.x * blockDim.x + threadIdx.x;
    const int seq = tid >> 4;
    const int s   = tid & 15;
    const int b   = seq >> 10;
    const int h   = seq & (HDIM - 1);

    const float a  = -__expf(flog[h * SDIM + s]);
    const float gh = g[h];

    const float* dtp = dt + (size_t)b * LDIM * HDIM + h;
    const float* up  = u  + (size_t)b * LDIM * HDIM + h;
    const float* vp  = v  + (size_t)b * LDIM * HDIM + h;
    float*       yp  = y  + (size_t)b * LDIM * HDIM + h;
    const float* zcp = zc + (size_t)b * LDIM * ZCW;

    float x = 0.f;
    float d_c  = dtp[0];
    float u_c  = up[0];
    float b_c  = zcp[RDIM + s];
    float c_c  = zcp[RDIM + SDIM + s];

    #pragma unroll 2
    for (int t = 0; t < LDIM; t++) {
        float d_n = 0.f, u_n = 0.f, b_n = 0.f, c_n = 0.f;
        if (t + 1 < LDIM) {
            const int tn = t + 1;
            d_n = dtp[tn * HDIM];
            u_n = up [tn * HDIM];
            b_n = zcp[tn * ZCW + RDIM + s];
            c_n = zcp[tn * ZCW + RDIM + SDIM + s];
        }
        const float aa = __expf(d_c * a);
        x = aa * x + (d_c * u_c) * b_c;
        float ys = x * c_c;
        ys += __shfl_xor_sync(0xffffffffu, ys, 8);
        ys += __shfl_xor_sync(0xffffffffu, ys, 4);
        ys += __shfl_xor_sync(0xffffffffu, ys, 2);
        ys += __shfl_xor_sync(0xffffffffu, ys, 1);
        if (s == 0) {
            const float vv = vp[t * HDIM];
            const float sv = vv * (1.0f / (1.0f + __expf(-vv)));
            yp[t * HDIM] = (ys + u_c * gh) * sv;
        }
        d_c = d_n; u_c = u_n; b_c = b_n; c_c = c_n;
    }
}

// ---------------------------------------------------------------------------
// Launch
// ---------------------------------------------------------------------------
extern "C" void kernel_launch(void* const* d_in, const int* in_sizes, int n_in,
                              void* d_out, int out_size)
{
    const float* x      = (const float*)d_in[0];
    const float* ctx    = (const float*)d_in[1];
    const float* Wa     = (const float*)d_in[2];
    const float* ba     = (const float*)d_in[3];
    const float* conv_w = (const float*)d_in[4];
    const float* conv_b = (const float*)d_in[5];
    const float* Wc     = (const float*)d_in[6];
    const float* We     = (const float*)d_in[7];
    const float* be     = (const float*)d_in[8];
    const float* f_log  = (const float*)d_in[9];
    const float* g      = (const float*)d_in[10];
    const float* Wi     = (const float*)d_in[11];
    const float* bi     = (const float*)d_in[12];
    const float* ln_w   = (const float*)d_in[13];
    const float* ln_b   = (const float*)d_in[14];
    const float* Wgb    = (const float*)d_in[15];
    const float* bgb    = (const float*)d_in[16];
    const float* Wgc    = (const float*)d_in[17];
    const float* bgc    = (const float*)d_in[18];
    float* out = (float*)d_out;

    float *cln, *z, *upre, *v, *u, *zc, *dt, *y;
    cudaGetSymbolAddress((void**)&cln,  g_cln);
    cudaGetSymbolAddress((void**)&z,    g_z);
    cudaGetSymbolAddress((void**)&upre, g_upre);
    cudaGetSymbolAddress((void**)&v,    g_v);
    cudaGetSymbolAddress((void**)&u,    g_u);
    cudaGetSymbolAddress((void**)&zc,   g_zc);
    cudaGetSymbolAddress((void**)&dt,   g_dt);
    cudaGetSymbolAddress((void**)&y,    g_y);

    const int SM128 = 1024 + 2 * 16384 + 2 * 128 * 128;  // 66560
    const int SM64  = 1024 + 2 * 16384 + 2 *  64 * 128;  // 50176
    cudaFuncSetAttribute(mma_gemm<128, 0>, cudaFuncAttributeMaxDynamicSharedMemorySize, SM128);
    cudaFuncSetAttribute(mma_gemm<128, 1>, cudaFuncAttributeMaxDynamicSharedMemorySize, SM128);
    cudaFuncSetAttribute(mma_gemm<128, 2>, cudaFuncAttributeMaxDynamicSharedMemorySize, SM128);
    cudaFuncSetAttribute(mma_gemm<128, 4>, cudaFuncAttributeMaxDynamicSharedMemorySize, SM128);
    cudaFuncSetAttribute(mma_gemm<64, 3>,  cudaFuncAttributeMaxDynamicSharedMemorySize, SM64);

    // 1. LayerNorm(ctx)
    ln_kernel<<<MDIM, 128>>>(ctx, ln_w, ln_b, cln);

    // 2. z = x @ Wa^T + ba               [8192 x 2048], K=512
    mma_gemm<128, 0><<<dim3(2 * HDIM / 128, MDIM / 128), 256, SM128>>>(
        x, DDIM, Wa, DDIM, z, 2 * HDIM, DDIM, ba, nullptr, 0);

    // 3. u_pre = z_u * (1 + sigmoid(cln @ Wgb^T + bgb))
    mma_gemm<128, 1><<<dim3(HDIM / 128, MDIM / 128), 256, SM128>>>(
        cln, DDIM, Wgb, DDIM, upre, HDIM, DDIM, bgb, z, 2 * HDIM);

    // 4. v = z_v + cln @ Wgc^T + bgc
    mma_gemm<128, 2><<<dim3(HDIM / 128, MDIM / 128), 256, SM128>>>(
        cln, DDIM, Wgc, DDIM, v, HDIM, DDIM, bgc, z, 2 * HDIM);

    // 5. u = silu(causal_conv3(u_pre))
    conv_silu_kernel<<<(MDIM * HDIM) / 256, 256>>>(upre, conv_w, conv_b, u);

    // 6. zc = u @ Wc^T                   [8192 x 64], K=1024
    mma_gemm<64, 3><<<dim3(1, MDIM / 128), 256, SM64>>>(
        u, HDIM, Wc, HDIM, zc, ZCW, HDIM, nullptr, nullptr, 0);

    // 7. dt = softplus(zc[:, :32] @ We^T + be)   [8192 x 1024], K=32
    mma_gemm<128, 4><<<dim3(HDIM / 128, MDIM / 128), 256, SM128>>>(
        zc, ZCW, We, RDIM, dt, HDIM, RDIM, be, nullptr, 0);

    // 8. selective scan + silu(v) gate -> y
    scan_kernel<<<(BDIM * HDIM * SDIM) / 256, 256>>>(u, dt, zc, f_log, g, v, y);

    // 9. out = y @ Wi^T + bi             [8192 x 512], K=1024
    mma_gemm<128, 0><<<dim3(DDIM / 128, MDIM / 128), 256, SM128>>>(
        y, HDIM, Wi, HDIM, out, DDIM, HDIM, bi, nullptr, 0);
}